// round 4
// baseline (speedup 1.0000x reference)
#include <cuda_runtime.h>
#include <cstdint>

// ---------------------------------------------------------------------------
// Problem: x[B,2] f32, ws[10] f32, B = 16777216.
// 10 steps: nx0 = x0 - 0.1*x1
//           nx1 = x1 + 0.1*x0 - 0.1*x0^3 + 0.1*w*x1
//               = (1 + 0.1*w)*x1 + x0*(0.1 - 0.1*x0^2)      (Horner form)
// out = (tanh(100(x1-0.1)) - tanh(100(x1+0.1)) + 2)/2
//     = sigmoid(200(0.1-x1)) + sigmoid(-200(x1+0.1))        (no cancellation)
//     = 1/(1 + 2^(L*x1 - C)) + 1/(1 + 2^(L*x1 + C)),  L=200*log2(e), C=0.1*L
//       [first term uses 2^(-(L*x1... )) => implemented with sign flip below]
// ---------------------------------------------------------------------------

// Packed f32x2 ops (Blackwell sm_100+): one instruction = 2 fp32 lanes.
#define FMA2(d, a, b, c) \
    asm("fma.rn.f32x2 %0, %1, %2, %3;" : "=l"(d) : "l"(a), "l"(b), "l"(c))
#define MUL2(d, a, b) \
    asm("mul.rn.f32x2 %0, %1, %2;" : "=l"(d) : "l"(a), "l"(b))

__device__ unsigned long long g_a_packed[10];  // splat(1 + 0.1*ws[k])

__global__ void prep_kernel(const float* __restrict__ ws) {
    int i = threadIdx.x;
    if (i < 10) {
        float a = fmaf(0.1f, ws[i], 1.0f);
        unsigned int u = __float_as_uint(a);
        g_a_packed[i] = ((unsigned long long)u << 32) | (unsigned long long)u;
    }
}

__device__ __forceinline__ float ex2_approx(float x) {
    float r; asm("ex2.approx.f32 %0, %1;" : "=f"(r) : "f"(x)); return r;
}
__device__ __forceinline__ float rcp_approx(float x) {
    float r; asm("rcp.approx.f32 %0, %1;" : "=f"(r) : "f"(x)); return r;
}

// out = 1/(1+2^(-L*x1+C)) + 1/(1+2^(L*x1+C))
__device__ __forceinline__ float notch(float x1) {
    const float L = 288.53900817779268f;   // 200 * log2(e)
    const float C = 28.853900817779268f;   // 0.1 * L
    float p = fmaf(-L, x1, C);
    float q = fmaf( L, x1, C);
    float t1 = rcp_approx(ex2_approx(p) + 1.0f);
    float t2 = rcp_approx(ex2_approx(q) + 1.0f);
    return t1 + t2;
}

// 4 points per thread: two independent packed-f32x2 recurrence chains.
__global__ __launch_bounds__(256) void nn_kernel(
    const float4* __restrict__ x, float4* __restrict__ out, int n4)
{
    int i = blockIdx.x * blockDim.x + threadIdx.x;
    if (i >= n4) return;

    float4 va = x[2 * i];      // points 0,1
    float4 vb = x[2 * i + 1];  // points 2,3

    unsigned long long X0a, X1a, X0b, X1b;
    asm("mov.b64 %0, {%1, %2};" : "=l"(X0a) : "f"(va.x), "f"(va.z));
    asm("mov.b64 %0, {%1, %2};" : "=l"(X1a) : "f"(va.y), "f"(va.w));
    asm("mov.b64 %0, {%1, %2};" : "=l"(X0b) : "f"(vb.x), "f"(vb.z));
    asm("mov.b64 %0, {%1, %2};" : "=l"(X1b) : "f"(vb.y), "f"(vb.w));

    const unsigned long long C01  = 0x3DCCCCCD3DCCCCCDULL;  // splat(+0.1f)
    const unsigned long long NC01 = 0xBDCCCCCDBDCCCCCDULL;  // splat(-0.1f)

    #pragma unroll
    for (int k = 0; k < 10; k++) {
        unsigned long long A = g_a_packed[k];  // uniform (L1 broadcast)

        unsigned long long nx0a, sa, ina, wa, nx1a;
        unsigned long long nx0b, sb, inb, wb, nx1b;
        // Two independent chains interleaved for dual-issue latency hiding.
        FMA2(nx0a, X1a, NC01, X0a);
        FMA2(nx0b, X1b, NC01, X0b);
        MUL2(sa,   X0a, X0a);
        MUL2(sb,   X0b, X0b);
        FMA2(ina,  sa,  NC01, C01);
        FMA2(inb,  sb,  NC01, C01);
        MUL2(wa,   ina, X0a);
        MUL2(wb,   inb, X0b);
        FMA2(nx1a, X1a, A, wa);
        FMA2(nx1b, X1b, A, wb);
        X0a = nx0a; X1a = nx1a;
        X0b = nx0b; X1b = nx1b;
    }

    float x1_0, x1_1, x1_2, x1_3;
    asm("mov.b64 {%0, %1}, %2;" : "=f"(x1_0), "=f"(x1_1) : "l"(X1a));
    asm("mov.b64 {%0, %1}, %2;" : "=f"(x1_2), "=f"(x1_3) : "l"(X1b));

    float4 o;
    o.x = notch(x1_0);
    o.y = notch(x1_1);
    o.z = notch(x1_2);
    o.w = notch(x1_3);
    out[i] = o;  // 16B coalesced store of 4 outputs
}

extern "C" void kernel_launch(void* const* d_in, const int* in_sizes, int n_in,
                              void* d_out, int out_size) {
    // Robust input identification: ws is the 10-element tensor.
    const float* x;
    const float* ws;
    if (n_in >= 2 && in_sizes[0] == 10) {
        ws = (const float*)d_in[0];
        x  = (const float*)d_in[1];
    } else {
        x  = (const float*)d_in[0];
        ws = (const float*)d_in[1];
    }

    prep_kernel<<<1, 32>>>(ws);

    int n4 = out_size / 4;  // 4 points per thread (B = 2^24, divisible)
    int blocks = (n4 + 255) / 256;
    nn_kernel<<<blocks, 256>>>((const float4*)x, (float4*)d_out, n4);
}

// round 5
// speedup vs baseline: 1.2398x; 1.2398x over previous
#include <cuda_runtime.h>
#include <cstdint>

// ---------------------------------------------------------------------------
// Problem: x[B,2] f32, ws[10] f32, B = 16777216.
//   step: nx0 = x0 - 0.1*x1
//         nx1 = (1 + 0.1*w)*x1 + 0.1*x0 - 0.1*x0^3
//   out  = (tanh(100(x1-0.1)) - tanh(100(x1+0.1)) + 2)/2
//
// Rescaled state (exact up to f32 rounding): x0 = 10*p,  x1 = -100*nq
//   p'  = p + nq                      (was p - q; we track nq = -q)
//   nq' = A*nq + nw,  nw = p*(p^2 - 0.01),  A = 1 + 0.1*w
// This removes the 0.1 multipliers from the hot loop: 3 of 5 packed ops now
// have <=2 distinct 64-bit sources (rt=2 on the banked fp32 pipe) instead of
// three 3-source FFMA2s (rt=3). Epilogue in terms of nq:
//   100*x1 -+ 10 = -10000*nq -+ 10  -> FFMA-imm (rt=1) + MUFU.TANH
// ---------------------------------------------------------------------------

#define FMA2(d, a, b, c) \
    asm("fma.rn.f32x2 %0, %1, %2, %3;" : "=l"(d) : "l"(a), "l"(b), "l"(c))
#define MUL2(d, a, b) \
    asm("mul.rn.f32x2 %0, %1, %2;" : "=l"(d) : "l"(a), "l"(b))
#define ADD2(d, a, b) \
    asm("add.rn.f32x2 %0, %1, %2;" : "=l"(d) : "l"(a), "l"(b))

__device__ unsigned long long g_a_packed[10];  // splat(1 + 0.1*ws[k])

__global__ void prep_kernel(const float* __restrict__ ws) {
    int i = threadIdx.x;
    if (i < 10) {
        float a = fmaf(0.1f, ws[i], 1.0f);
        unsigned int u = __float_as_uint(a);
        g_a_packed[i] = ((unsigned long long)u << 32) | (unsigned long long)u;
    }
}

__device__ __forceinline__ float tanh_approx(float x) {
    float r; asm("tanh.approx.f32 %0, %1;" : "=f"(r) : "f"(x)); return r;
}

// out = 0.5*tanh(-10000*nq - 10) - 0.5*tanh(-10000*nq + 10) + 1
// (all four fp ops are FFMA with immediate multiplier -> rt_SMSP = 1)
__device__ __forceinline__ float notch_nq(float nq) {
    float t1 = tanh_approx(fmaf(-10000.0f, nq, -10.0f));
    float t2 = tanh_approx(fmaf(-10000.0f, nq,  10.0f));
    return fmaf(0.5f, t1, fmaf(-0.5f, t2, 1.0f));
}

// 4 points per thread: two independent packed-f32x2 recurrence chains.
__global__ __launch_bounds__(256) void nn_kernel(
    const float4* __restrict__ x, float4* __restrict__ out, int n4)
{
    int i = blockIdx.x * blockDim.x + threadIdx.x;
    if (i >= n4) return;

    float4 va = x[2 * i];      // points 0,1
    float4 vb = x[2 * i + 1];  // points 2,3

    unsigned long long X0a, X1a, X0b, X1b;
    asm("mov.b64 %0, {%1, %2};" : "=l"(X0a) : "f"(va.x), "f"(va.z));
    asm("mov.b64 %0, {%1, %2};" : "=l"(X1a) : "f"(va.y), "f"(va.w));
    asm("mov.b64 %0, {%1, %2};" : "=l"(X0b) : "f"(vb.x), "f"(vb.z));
    asm("mov.b64 %0, {%1, %2};" : "=l"(X1b) : "f"(vb.y), "f"(vb.w));

    const unsigned long long C01   = 0x3DCCCCCD3DCCCCCDULL;  // splat(+0.1f)
    const unsigned long long NC001 = 0xBC23D70ABC23D70AULL;  // splat(-0.01f)

    // Scale into (p, nq): p = 0.1*x0, nq = -0.01*x1
    unsigned long long Pa, NQa, Pb, NQb;
    MUL2(Pa,  X0a, C01);
    MUL2(NQa, X1a, NC001);
    MUL2(Pb,  X0b, C01);
    MUL2(NQb, X1b, NC001);

    #pragma unroll
    for (int k = 0; k < 10; k++) {
        unsigned long long A = g_a_packed[k];  // uniform (L1 broadcast)

        unsigned long long sa, ina, nwa, pa2, nqa2;
        unsigned long long sb, inb, nwb, pb2, nqb2;
        // Two independent chains interleaved for dual-issue latency hiding.
        MUL2(sa,   Pa, Pa);           // p^2                 (1 src  -> rt2)
        MUL2(sb,   Pb, Pb);
        ADD2(ina,  sa, NC001);        // p^2 - 0.01          (2 src  -> rt2)
        ADD2(inb,  sb, NC001);
        MUL2(nwa,  ina, Pa);          // p^3 - 0.01p = -w    (2 src  -> rt2)
        MUL2(nwb,  inb, Pb);
        ADD2(pa2,  Pa, NQa);          // p' = p - q          (2 src  -> rt2)
        ADD2(pb2,  Pb, NQb);
        FMA2(nqa2, A, NQa, nwa);      // nq' = A*nq - w      (3 src  -> rt3)
        FMA2(nqb2, A, NQb, nwb);
        Pa = pa2;  NQa = nqa2;
        Pb = pb2;  NQb = nqb2;
    }

    float nq0, nq1, nq2, nq3;
    asm("mov.b64 {%0, %1}, %2;" : "=f"(nq0), "=f"(nq1) : "l"(NQa));
    asm("mov.b64 {%0, %1}, %2;" : "=f"(nq2), "=f"(nq3) : "l"(NQb));

    float4 o;
    o.x = notch_nq(nq0);
    o.y = notch_nq(nq1);
    o.z = notch_nq(nq2);
    o.w = notch_nq(nq3);
    out[i] = o;  // 16B coalesced store of 4 outputs
}

extern "C" void kernel_launch(void* const* d_in, const int* in_sizes, int n_in,
                              void* d_out, int out_size) {
    // Robust input identification: ws is the 10-element tensor.
    const float* x;
    const float* ws;
    if (n_in >= 2 && in_sizes[0] == 10) {
        ws = (const float*)d_in[0];
        x  = (const float*)d_in[1];
    } else {
        x  = (const float*)d_in[0];
        ws = (const float*)d_in[1];
    }

    prep_kernel<<<1, 32>>>(ws);

    int n4 = out_size / 4;  // 4 points per thread (B = 2^24, divisible)
    int blocks = (n4 + 255) / 256;
    nn_kernel<<<blocks, 256>>>((const float4*)x, (float4*)d_out, n4);
}